// round 16
// baseline (speedup 1.0000x reference)
#include <cuda_runtime.h>
#include <math.h>
#include <stdint.h>

// ---------------------------------------------------------------------------
// 2-layer LSTM (T=1024, B=128, E=58, H=256) + Linear(256->33) + softplus.
//
// R16 = R13 components, 5-phase slot:
//   S  : stage A0:=y0(t-1) (thr 0-127) and A1:=y1(t-2) (thr 128-255);
//        exactly ONE acquire-poll per thread, then 8 batched LDG -> STS.
//   G  : all three gemm32 (L0h, L1x, L1h) in one phase.
//   W  : P0 := hadd(acc0), P1 := hadd(acc1)   (P aliases A, barrier-safe)
//   E0 : epi0 -> y0(t), publish flag0
//   E1 : epi1 -> y1(t-1), publish flag1
// 5 barriers/slot (R13 had 7), no exposed mid-slot staging. GEMM inner loop,
// epilogue math, flag protocol identical to R13 (the proven 9.62ms kernel).
// ---------------------------------------------------------------------------

namespace {
constexpr int TT = 1024;
constexpr int BB = 128;
constexpr int EE = 58;
constexpr int HH = 256;
constexpr int OO = 33;

constexpr int HT = 16;             // hidden units per CTA
constexpr int BT = 16;             // batch per CTA
constexpr int HS = HH / HT;        // 16 hidden slices
constexpr int NCTA = 128;          // 16 x 8
constexpr int NTHR = 256;
constexpr int HP = HH / 2;         // 128 k-pairs
constexpr int PJ = 68;             // Part row stride (floats)
constexpr int REG_BYTES = 4 * 16 * PJ * 4;   // 17,408 per A/P union region
}

// Scratch (static __device__: allocation-free per harness rules)
__device__ float2 g_y0[(size_t)TT * HP * BB];   // [t][hpair][b]
__device__ float2 g_y1[(size_t)TT * HP * BB];
__device__ float  g_xp0[(size_t)TT * BB * HH * 4];  // [t][b][h][gate]
__device__ unsigned g_flags[2 * NCTA];

__global__ void reset_kernel() {
    int i = threadIdx.x;
    if (i < 2 * NCTA) g_flags[i] = 0u;
}

__device__ __forceinline__ void ffma2(uint64_t& d, uint64_t a, uint64_t b) {
    asm("fma.rn.f32x2 %0, %1, %2, %0;" : "+l"(d) : "l"(a), "l"(b));
}
__device__ __forceinline__ float fast_sigmoid(float x) {
    return __fdividef(1.f, 1.f + __expf(-x));
}
__device__ __forceinline__ float fast_tanh(float x) {
    float t = __expf(-2.f * fabsf(x));
    float r = __fdividef(1.f - t, 1.f + t);
    return copysignf(r, x);
}
__device__ __forceinline__ void poll1(const unsigned* fp, unsigned target) {
    unsigned v;
    do {
        asm volatile("ld.acquire.gpu.global.u32 %0, [%1];" : "=r"(v) : "l"(fp));
    } while (v < target);
}

// ---------------------------------------------------------------------------
// xp0 precompute: xp0[t][b][h][g] = sum_e x[t][b][e]*W_ih0[g*H+h][e] + biases
// ---------------------------------------------------------------------------
__global__ void __launch_bounds__(256)
xp0_kernel(const float* __restrict__ x,       // [T][B][E]
           const float* __restrict__ W_ih0,   // [4H][E]
           const float* __restrict__ b_ih0,
           const float* __restrict__ b_hh0) {
    __shared__ float xs[64][EE];
    __shared__ float ws[4][32][EE];
    __shared__ float bs[4][32];
    const int t = blockIdx.x;
    const int hbase = blockIdx.y * 32;
    const int bbase = blockIdx.z * 64;
    const int tid = threadIdx.x;

    for (int i = tid; i < 64 * EE; i += 256) {
        int b = i / EE, e = i - b * EE;
        xs[b][e] = x[((size_t)t * BB + bbase + b) * EE + e];
    }
    for (int i = tid; i < 4 * 32 * EE; i += 256) {
        int e = i % EE; int r = i / EE; int g = r >> 5, hh = r & 31;
        ws[g][hh][e] = W_ih0[(size_t)(g * HH + hbase + hh) * EE + e];
    }
    if (tid < 128) {
        int g = tid >> 5, hh = tid & 31;
        bs[g][hh] = b_ih0[g * HH + hbase + hh] + b_hh0[g * HH + hbase + hh];
    }
    __syncthreads();

    const int bb = tid >> 3;
    const int hq = tid & 7;
    float acc[2][4][4] = {};
    for (int e = 0; e < EE; e++) {
        float x0 = xs[bb * 2][e], x1 = xs[bb * 2 + 1][e];
        #pragma unroll
        for (int h = 0; h < 4; h++)
            #pragma unroll
            for (int g = 0; g < 4; g++) {
                float w = ws[g][hq * 4 + h][e];
                acc[0][h][g] += x0 * w;
                acc[1][h][g] += x1 * w;
            }
    }
    #pragma unroll
    for (int bi = 0; bi < 2; bi++)
        #pragma unroll
        for (int h = 0; h < 4; h++) {
            float4 v;
            v.x = acc[bi][h][0] + bs[0][hq * 4 + h];
            v.y = acc[bi][h][1] + bs[1][hq * 4 + h];
            v.z = acc[bi][h][2] + bs[2][hq * 4 + h];
            v.w = acc[bi][h][3] + bs[3][hq * 4 + h];
            *(float4*)&g_xp0[(((size_t)t * BB + bbase + bb * 2 + bi) * HH
                              + hbase + hq * 4 + h) * 4] = v;
        }
}

// 32 k-pairs GEMM: 4 cols x 4 batches per thread (f32x2 even/odd-k partials).
__device__ __forceinline__ void gemm32(const float2* __restrict__ Wb,
                                       const float2* __restrict__ Ab,
                                       uint64_t acc[4][4]) {
    const char* wp = (const char*)Wb;
    const char* ip = (const char*)Ab;
    #pragma unroll 4
    for (int k = 0; k < 32; k++) {
        const ulonglong2 w01 = *(const ulonglong2*)(wp);
        const ulonglong2 w23 = *(const ulonglong2*)(wp + 16);
        const ulonglong2 i01 = *(const ulonglong2*)(ip);
        const ulonglong2 i23 = *(const ulonglong2*)(ip + 16);
        ffma2(acc[0][0], w01.x, i01.x); ffma2(acc[1][0], w01.y, i01.x);
        ffma2(acc[2][0], w23.x, i01.x); ffma2(acc[3][0], w23.y, i01.x);
        ffma2(acc[0][1], w01.x, i01.y); ffma2(acc[1][1], w01.y, i01.y);
        ffma2(acc[2][1], w23.x, i01.y); ffma2(acc[3][1], w23.y, i01.y);
        ffma2(acc[0][2], w01.x, i23.x); ffma2(acc[1][2], w01.y, i23.x);
        ffma2(acc[2][2], w23.x, i23.x); ffma2(acc[3][2], w23.y, i23.x);
        ffma2(acc[0][3], w01.x, i23.y); ffma2(acc[1][3], w01.y, i23.y);
        ffma2(acc[2][3], w23.x, i23.y); ffma2(acc[3][3], w23.y, i23.y);
        wp += 512;
        ip += 128;
    }
}

__device__ __forceinline__ void part_write(float* P, int kg, int b2, int jt,
                                           const uint64_t acc[4][4]) {
    float* pb = P + kg * (16 * PJ) + b2 * PJ + jt * 4;
    #pragma unroll
    for (int bi = 0; bi < 4; bi++) {
        union { uint64_t u; float2 f; } a0, a1, a2, a3;
        a0.u = acc[0][bi]; a1.u = acc[1][bi];
        a2.u = acc[2][bi]; a3.u = acc[3][bi];
        float4 v;
        v.x = a0.f.x + a0.f.y; v.y = a1.f.x + a1.f.y;
        v.z = a2.f.x + a2.f.y; v.w = a3.f.x + a3.f.y;
        *(float4*)(pb + bi * PJ) = v;
    }
}

__global__ void __launch_bounds__(NTHR, 1)
lstm_fused_kernel(const float* __restrict__ W_hh0,  // (4H, H)
                  const float* __restrict__ W_ih1,  // (4H, H)
                  const float* __restrict__ W_hh1,  // (4H, H)
                  const float* __restrict__ b_ih1,
                  const float* __restrict__ b_hh1,
                  const float* __restrict__ h0,     // (2, B, H)
                  const float* __restrict__ c0,     // (2, B, H)
                  float* __restrict__ hn,           // (2, B, H)
                  float* __restrict__ cn)           // (2, B, H)
{
    extern __shared__ float2 smp[];
    float2* Wp0 = smp;                        // [128][64]  65,536 B
    float2* Wp1 = Wp0 + 128 * 64;             // [256][64] 131,072 B
    char*   R0  = (char*)(Wp1 + 256 * 64);    // 17,408 B: A0 | P0
    char*   R1  = R0 + REG_BYTES;             // 17,408 B: A1 | P1
    float2* A0  = (float2*)R0;   float* P0 = (float*)R0;
    float2* A1  = (float2*)R1;   float* P1 = (float*)R1;

    const int tid   = threadIdx.x;
    const int lane  = tid & 31;
    const int cta   = blockIdx.x;
    const int hsl   = cta & (HS - 1);
    const int bsl   = cta >> 4;
    const int hbase = hsl * HT;
    const int bbase = bsl * BT;

    // ---- stage weight slices once ----
    for (int i = tid; i < 128 * 64; i += NTHR) {
        int jl = i >> 7;
        int kp = i & 127;
        int gate = jl >> 4, hh = jl & 15;
        int row = gate * HH + hbase + hh;
        Wp0[(size_t)kp * 64 + jl] = ((const float2*)(W_hh0 + (size_t)row * HH))[kp];
    }
    for (int i = tid; i < 256 * 64; i += NTHR) {
        int jl = i >> 8;
        int kp = i & 255;
        int gate = jl >> 4, hh = jl & 15;
        int row = gate * HH + hbase + hh;
        float2 w = (kp < 128)
            ? ((const float2*)(W_ih1 + (size_t)row * HH))[kp]
            : ((const float2*)(W_hh1 + (size_t)row * HH))[kp - 128];
        Wp1[(size_t)kp * 64 + jl] = w;
    }

    // ---- GEMM mapping (R13-proven): 8 warps = 4 kgroups x 2 batch halves ----
    const int wrp = tid >> 5;
    const int kg  = wrp >> 1;
    const int bh  = wrp & 1;
    const int jt  = lane >> 1;
    const int bq  = lane & 1;
    const int b2  = bh * 8 + bq * 4;
    const size_t wOff = (size_t)(kg * 32) * 64 + jt * 4;
    const size_t aOff = (size_t)(kg * 32) * 16 + b2;

    // ---- staging map: 128 threads per buffer, ONE flag poll per thread ----
    // thread st (0..127): sf = st>>3 (flag idx), sw = st&7 (batch pair).
    // item i (0..7): kp = 8*sf + i, bp = sw.
    // STS pattern: warp lanes at item i cover 4 kp-rows x 8 bp = conflict-free.
    const int sg = tid >> 7;          // 0: stages A0,  1: stages A1
    const int st = tid & 127;
    const int sf = st >> 3;           // producer flag / kp-block index
    const int sw = st & 7;
    const size_t gBase = (size_t)(8 * sf) * BB + bbase + sw * 2;  // float2 units
    const int    sBase = (8 * sf) * 8 + sw;                        // uint4 units

    // ---- epilogue mapping ----
    const int eb = tid >> 4;
    const int eh = tid & 15;
    const float bias1_0 = b_ih1[0 * HH + hbase + eh] + b_hh1[0 * HH + hbase + eh];
    const float bias1_1 = b_ih1[1 * HH + hbase + eh] + b_hh1[1 * HH + hbase + eh];
    const float bias1_2 = b_ih1[2 * HH + hbase + eh] + b_hh1[2 * HH + hbase + eh];
    const float bias1_3 = b_ih1[3 * HH + hbase + eh] + b_hh1[3 * HH + hbase + eh];
    float c0acc = c0[(bbase + eb) * HH + hbase + eh];
    float c1acc = c0[(size_t)BB * HH + (bbase + eb) * HH + hbase + eh];

    const unsigned* flg0_grp = &g_flags[bsl * HS];
    const unsigned* flg1_grp = &g_flags[NCTA + bsl * HS];
    unsigned* flg0_self = &g_flags[cta];
    unsigned* flg1_self = &g_flags[NCTA + cta];

    __syncthreads();   // weights staged

    for (int t = 0; t <= TT; t++) {
        // ============ Phase S: stage A0 and A1 concurrently ============
        if (t == 0) {
            // A0 := h0 layer0 (all threads); no L1 yet
            for (int i = tid; i < 128 * 16; i += NTHR) {
                int kp = i >> 4, b = i & 15;
                A0[kp * 16 + b] = ((const float2*)h0)[(size_t)(bbase + b) * HP + kp];
            }
        } else if (sg == 0) {
            // A0 := y0(t-1); one acquire, then 8 batched LDG -> STS
            poll1(flg0_grp + sf, (unsigned)t);
            const float2* src = g_y0 + (size_t)(t - 1) * HP * BB + gBase;
            uint4 r[8];
            #pragma unroll
            for (int i = 0; i < 8; i++)
                r[i] = *(const uint4*)(src + (size_t)i * BB);
            uint4* dst = (uint4*)A0 + sBase;
            #pragma unroll
            for (int i = 0; i < 8; i++)
                dst[i * 8] = r[i];
        } else {
            if (t == 1) {
                // A1 := h0 layer1 (128 threads)
                const float2* h1i = (const float2*)(h0 + (size_t)BB * HH);
                for (int i = st; i < 128 * 16; i += 128) {
                    int kp = i >> 4, b = i & 15;
                    A1[kp * 16 + b] = h1i[(size_t)(bbase + b) * HP + kp];
                }
            } else {
                // A1 := y1(t-2)
                poll1(flg1_grp + sf, (unsigned)(t - 1));
                const float2* src = g_y1 + (size_t)(t - 2) * HP * BB + gBase;
                uint4 r[8];
                #pragma unroll
                for (int i = 0; i < 8; i++)
                    r[i] = *(const uint4*)(src + (size_t)i * BB);
                uint4* dst = (uint4*)A1 + sBase;
                #pragma unroll
                for (int i = 0; i < 8; i++)
                    dst[i * 8] = r[i];
            }
        }
        __syncthreads();   // SYNC1

        // ============ Phase G: all three GEMMs ============
        uint4 xpv = make_uint4(0u, 0u, 0u, 0u);
        if (t < TT)        // lands long before E0 consumes it
            xpv = *(const uint4*)&g_xp0[(((size_t)t * BB + bbase + eb) * HH
                                         + hbase + eh) * 4];
        uint64_t acc0[4][4] = {};
        uint64_t acc1[4][4] = {};
        if (t < TT) gemm32(Wp0 + wOff, A0 + aOff, acc0);                 // L0 h
        if (t > 0) {
            gemm32(Wp1 + wOff, A0 + aOff, acc1);                         // L1 x
            gemm32(Wp1 + (size_t)128 * 64 + wOff, A1 + aOff, acc1);      // L1 h
        }
        __syncthreads();   // SYNC2  (A0/A1 reads done -> P regions free)

        // ============ Phase W: partials ============
        if (t < TT) part_write(P0, kg, b2, jt, acc0);
        if (t > 0)  part_write(P1, kg, b2, jt, acc1);
        __syncthreads();   // SYNC3

        // ============ Phase E0: epi0 -> y0(t) ============
        if (t < TT) {
            float4 xf = *(float4*)&xpv;
            float s0 = xf.x, s1 = xf.y, s2 = xf.z, s3 = xf.w;
            #pragma unroll
            for (int p = 0; p < 4; p++) {
                const float* pp = P0 + p * (16 * PJ) + eb * PJ;
                s0 += pp[ 0 + eh];
                s1 += pp[16 + eh];
                s2 += pp[32 + eh];
                s3 += pp[48 + eh];
            }
            const float ig = fast_sigmoid(s0);
            const float fg = fast_sigmoid(s1);
            const float gt = fast_tanh(s2);
            const float og = fast_sigmoid(s3);
            c0acc = fg * c0acc + ig * gt;
            const float hv = og * fast_tanh(c0acc);
            const float hv1 = __shfl_down_sync(0xffffffffu, hv, 1);
            if (!(eh & 1))
                g_y0[(size_t)t * HP * BB + ((hbase + eh) >> 1) * BB + (bbase + eb)] =
                    make_float2(hv, hv1);
            if (t == TT - 1) {
                hn[(bbase + eb) * HH + hbase + eh] = hv;
                cn[(bbase + eb) * HH + hbase + eh] = c0acc;
            }
        }
        __syncthreads();   // SYNC4  (y0 stores + P0 reads done)
        if (tid == 0 && t < TT)
            asm volatile("st.release.gpu.global.u32 [%0], %1;"
                         :: "l"(flg0_self), "r"((unsigned)(t + 1)) : "memory");

        // ============ Phase E1: epi1 -> y1(t-1) ============
        if (t > 0) {
            float s0 = bias1_0, s1 = bias1_1, s2 = bias1_2, s3 = bias1_3;
            #pragma unroll
            for (int p = 0; p < 4; p++) {
                const float* pp = P1 + p * (16 * PJ) + eb * PJ;
                s0 += pp[ 0 + eh];
                s1 += pp[16 + eh];
                s2 += pp[32 + eh];
                s3 += pp[48 + eh];
            }
            const float ig = fast_sigmoid(s0);
            const float fg = fast_sigmoid(s1);
            const float gt = fast_tanh(s2);
            const float og = fast_sigmoid(s3);
            c1acc = fg * c1acc + ig * gt;
            const float hv = og * fast_tanh(c1acc);
            const float hv1 = __shfl_down_sync(0xffffffffu, hv, 1);
            if (!(eh & 1))
                g_y1[(size_t)(t - 1) * HP * BB + ((hbase + eh) >> 1) * BB + (bbase + eb)] =
                    make_float2(hv, hv1);
            if (t == TT) {
                hn[(size_t)BB * HH + (bbase + eb) * HH + hbase + eh] = hv;
                cn[(size_t)BB * HH + (bbase + eb) * HH + hbase + eh] = c1acc;
            }
        }
        __syncthreads();   // SYNC5  (y1 stores + P1 reads done)
        if (tid == 0 && t > 0)
            asm volatile("st.release.gpu.global.u32 [%0], %1;"
                         :: "l"(flg1_self), "r"((unsigned)t) : "memory");
    }
}

// Final projection + softplus: out[t][b][o] = softplus(y1[t]·W_out^T + b_out)
__global__ void __launch_bounds__(128, 4)
proj_kernel(const float* __restrict__ W_out,  // (33, 256)
            const float* __restrict__ b_out,  // (33,)
            float* __restrict__ out)          // [T][B][33]
{
    __shared__ float Wsm[HH * OO];
    const int t = blockIdx.x;
    const int b = threadIdx.x;

    for (int i = b; i < HH * OO; i += 128) {
        int k = i / OO;
        int o = i - k * OO;
        Wsm[k * OO + o] = W_out[o * HH + k];
    }
    __syncthreads();

    const float2* y = g_y1 + (size_t)t * HP * BB;
    float acc[OO];
    #pragma unroll
    for (int o = 0; o < OO; o++) acc[o] = b_out[o];

    #pragma unroll 2
    for (int kp = 0; kp < HP; kp++) {
        const float2 v = y[kp * BB + b];
        const float* w0 = &Wsm[(2 * kp) * OO];
        const float* w1 = &Wsm[(2 * kp + 1) * OO];
        #pragma unroll
        for (int o = 0; o < OO; o++) acc[o] += v.x * w0[o] + v.y * w1[o];
    }

    float* op = out + (size_t)t * BB * OO + b * OO;
    #pragma unroll
    for (int o = 0; o < OO; o++) {
        const float x = acc[o];
        op[o] = fmaxf(x, 0.f) + log1pf(__expf(-fabsf(x)));
    }
}

extern "C" void kernel_launch(void* const* d_in, const int* in_sizes, int n_in,
                              void* d_out, int out_size) {
    const float* x     = (const float*)d_in[0];
    const float* h0    = (const float*)d_in[1];
    const float* c0    = (const float*)d_in[2];
    const float* W_ih0 = (const float*)d_in[3];
    const float* W_hh0 = (const float*)d_in[4];
    const float* b_ih0 = (const float*)d_in[5];
    const float* b_hh0 = (const float*)d_in[6];
    const float* W_ih1 = (const float*)d_in[7];
    const float* W_hh1 = (const float*)d_in[8];
    const float* b_ih1 = (const float*)d_in[9];
    const float* b_hh1 = (const float*)d_in[10];
    const float* W_out = (const float*)d_in[11];
    const float* b_out = (const float*)d_in[12];

    float* out = (float*)d_out;
    float* hn  = out + (size_t)TT * BB * OO;   // (2,B,H)
    float* cn  = hn + 2 * BB * HH;             // (2,B,H)

    // smem: Wp0 65,536 + Wp1 131,072 + 2 x 17,408 = 231,424 B
    const int smemF = 128 * 64 * 8 + 256 * 64 * 8 + 2 * REG_BYTES;
    cudaFuncSetAttribute((const void*)lstm_fused_kernel,
                         cudaFuncAttributeMaxDynamicSharedMemorySize, smemF);

    reset_kernel<<<1, 256>>>();

    dim3 xg(TT, 8, 2);
    xp0_kernel<<<xg, 256>>>(x, W_ih0, b_ih0, b_hh0);

    lstm_fused_kernel<<<NCTA, NTHR, smemF>>>(
        W_hh0, W_ih1, W_hh1, b_ih1, b_hh1, h0, c0, hn, cn);

    proj_kernel<<<TT, 128>>>(W_out, b_out, out);
}

// round 17
// speedup vs baseline: 1.3680x; 1.3680x over previous
#include <cuda_runtime.h>
#include <math.h>
#include <stdint.h>

// ---------------------------------------------------------------------------
// 2-layer LSTM (T=1024, B=128, E=58, H=256) + Linear(256->33) + softplus.
//
// R17 = R13 (the proven 9.62ms kernel) VERBATIM except ONE change:
//   the y1(t-2) restage LDG (previously exposed in the SYNC2->SYNC3 phase)
//   is issued into registers at the end of the staging phase and lands under
//   the ~4K-cycle GEMM phase; the W phase is now a pure STS from registers.
// Ordering: the flg1 >= t-1 acquire already happens in the poll phase
// (before SYNC0), and bar.sync propagates visibility CTA-wide — identical
// guarantee to R13, just earlier issue of the dependent loads.
// ---------------------------------------------------------------------------

namespace {
constexpr int TT = 1024;
constexpr int BB = 128;
constexpr int EE = 58;
constexpr int HH = 256;
constexpr int OO = 33;

constexpr int HT = 16;             // hidden units per CTA
constexpr int BT = 16;             // batch per CTA
constexpr int HS = HH / HT;        // 16 hidden slices
constexpr int NCTA = 128;          // 16 x 8
constexpr int NTHR = 256;
constexpr int HP = HH / 2;         // 128 k-pairs
constexpr int PJ = 68;             // Part row stride (floats)
}

// Scratch (static __device__: allocation-free per harness rules)
__device__ float2 g_y0[(size_t)TT * HP * BB];   // [t][hpair][b]
__device__ float2 g_y1[(size_t)TT * HP * BB];
__device__ float  g_xp0[(size_t)TT * BB * HH * 4];  // [t][b][h][gate]
__device__ unsigned g_flags[2 * NCTA];

__global__ void reset_kernel() {
    int i = threadIdx.x;
    if (i < 2 * NCTA) g_flags[i] = 0u;
}

__device__ __forceinline__ void ffma2(uint64_t& d, uint64_t a, uint64_t b) {
    asm("fma.rn.f32x2 %0, %1, %2, %0;" : "+l"(d) : "l"(a), "l"(b));
}
__device__ __forceinline__ float fast_sigmoid(float x) {
    return __fdividef(1.f, 1.f + __expf(-x));
}
__device__ __forceinline__ float fast_tanh(float x) {
    float t = __expf(-2.f * fabsf(x));
    float r = __fdividef(1.f - t, 1.f + t);
    return copysignf(r, x);
}

// ---------------------------------------------------------------------------
// xp0 precompute: xp0[t][b][h][g] = sum_e x[t][b][e]*W_ih0[g*H+h][e] + biases
// ---------------------------------------------------------------------------
__global__ void __launch_bounds__(256)
xp0_kernel(const float* __restrict__ x,       // [T][B][E]
           const float* __restrict__ W_ih0,   // [4H][E]
           const float* __restrict__ b_ih0,
           const float* __restrict__ b_hh0) {
    __shared__ float xs[64][EE];
    __shared__ float ws[4][32][EE];
    __shared__ float bs[4][32];
    const int t = blockIdx.x;
    const int hbase = blockIdx.y * 32;
    const int bbase = blockIdx.z * 64;
    const int tid = threadIdx.x;

    for (int i = tid; i < 64 * EE; i += 256) {
        int b = i / EE, e = i - b * EE;
        xs[b][e] = x[((size_t)t * BB + bbase + b) * EE + e];
    }
    for (int i = tid; i < 4 * 32 * EE; i += 256) {
        int e = i % EE; int r = i / EE; int g = r >> 5, hh = r & 31;
        ws[g][hh][e] = W_ih0[(size_t)(g * HH + hbase + hh) * EE + e];
    }
    if (tid < 128) {
        int g = tid >> 5, hh = tid & 31;
        bs[g][hh] = b_ih0[g * HH + hbase + hh] + b_hh0[g * HH + hbase + hh];
    }
    __syncthreads();

    const int bb = tid >> 3;
    const int hq = tid & 7;
    float acc[2][4][4] = {};
    for (int e = 0; e < EE; e++) {
        float x0 = xs[bb * 2][e], x1 = xs[bb * 2 + 1][e];
        #pragma unroll
        for (int h = 0; h < 4; h++)
            #pragma unroll
            for (int g = 0; g < 4; g++) {
                float w = ws[g][hq * 4 + h][e];
                acc[0][h][g] += x0 * w;
                acc[1][h][g] += x1 * w;
            }
    }
    #pragma unroll
    for (int bi = 0; bi < 2; bi++)
        #pragma unroll
        for (int h = 0; h < 4; h++) {
            float4 v;
            v.x = acc[bi][h][0] + bs[0][hq * 4 + h];
            v.y = acc[bi][h][1] + bs[1][hq * 4 + h];
            v.z = acc[bi][h][2] + bs[2][hq * 4 + h];
            v.w = acc[bi][h][3] + bs[3][hq * 4 + h];
            *(float4*)&g_xp0[(((size_t)t * BB + bbase + bb * 2 + bi) * HH
                              + hbase + hq * 4 + h) * 4] = v;
        }
}

// 32 k-pairs GEMM: 4 cols x 4 batches per thread (f32x2 even/odd-k partials).
__device__ __forceinline__ void gemm32(const float2* __restrict__ Wb,
                                       const float2* __restrict__ Ab,
                                       uint64_t acc[4][4]) {
    const char* wp = (const char*)Wb;
    const char* ip = (const char*)Ab;
    #pragma unroll 4
    for (int k = 0; k < 32; k++) {
        const ulonglong2 w01 = *(const ulonglong2*)(wp);
        const ulonglong2 w23 = *(const ulonglong2*)(wp + 16);
        const ulonglong2 i01 = *(const ulonglong2*)(ip);
        const ulonglong2 i23 = *(const ulonglong2*)(ip + 16);
        ffma2(acc[0][0], w01.x, i01.x); ffma2(acc[1][0], w01.y, i01.x);
        ffma2(acc[2][0], w23.x, i01.x); ffma2(acc[3][0], w23.y, i01.x);
        ffma2(acc[0][1], w01.x, i01.y); ffma2(acc[1][1], w01.y, i01.y);
        ffma2(acc[2][1], w23.x, i01.y); ffma2(acc[3][1], w23.y, i01.y);
        ffma2(acc[0][2], w01.x, i23.x); ffma2(acc[1][2], w01.y, i23.x);
        ffma2(acc[2][2], w23.x, i23.x); ffma2(acc[3][2], w23.y, i23.x);
        ffma2(acc[0][3], w01.x, i23.y); ffma2(acc[1][3], w01.y, i23.y);
        ffma2(acc[2][3], w23.x, i23.y); ffma2(acc[3][3], w23.y, i23.y);
        wp += 512;
        ip += 128;
    }
}

__global__ void __launch_bounds__(NTHR, 1)
lstm_fused_kernel(const float* __restrict__ W_hh0,  // (4H, H)
                  const float* __restrict__ W_ih1,  // (4H, H)
                  const float* __restrict__ W_hh1,  // (4H, H)
                  const float* __restrict__ b_ih1,
                  const float* __restrict__ b_hh1,
                  const float* __restrict__ h0,     // (2, B, H)
                  const float* __restrict__ c0,     // (2, B, H)
                  float* __restrict__ hn,           // (2, B, H)
                  float* __restrict__ cn)           // (2, B, H)
{
    extern __shared__ float2 smp[];
    float2* Wp0 = smp;                      // [128][64]  W_hh0 k-pairs
    float2* Wp1 = Wp0 + 128 * 64;           // [256][64]  W_ih1 | W_hh1 k-pairs
    float2* A   = Wp1 + 256 * 64;           // [128][16]  shared input buffer
    float*  P   = (float*)(A + 128 * 16);   // [4][16][PJ] partials

    const int tid   = threadIdx.x;
    const int cta   = blockIdx.x;
    const int hsl   = cta & (HS - 1);
    const int bsl   = cta >> 4;
    const int hbase = hsl * HT;
    const int bbase = bsl * BT;

    // ---- stage weight slices once ----
    for (int i = tid; i < 128 * 64; i += NTHR) {
        int jl = i >> 7;
        int kp = i & 127;
        int gate = jl >> 4, hh = jl & 15;
        int row = gate * HH + hbase + hh;
        Wp0[(size_t)kp * 64 + jl] = ((const float2*)(W_hh0 + (size_t)row * HH))[kp];
    }
    for (int i = tid; i < 256 * 64; i += NTHR) {
        int jl = i >> 8;
        int kp = i & 255;
        int gate = jl >> 4, hh = jl & 15;
        int row = gate * HH + hbase + hh;
        float2 w = (kp < 128)
            ? ((const float2*)(W_ih1 + (size_t)row * HH))[kp]
            : ((const float2*)(W_hh1 + (size_t)row * HH))[kp - 128];
        Wp1[(size_t)kp * 64 + jl] = w;
    }

    // ---- GEMM mapping: 8 warps = 4 kgroups x 2 batch halves ----
    const int wrp = tid >> 5;
    const int kg  = wrp >> 1;
    const int bh  = wrp & 1;
    const int lane = tid & 31;
    const int jt  = lane >> 1;
    const int bq  = lane & 1;
    const int b2  = bh * 8 + bq * 4;
    const size_t wOff = (size_t)(kg * 32) * 64 + jt * 4;
    const size_t aOff = (size_t)(kg * 32) * 16 + b2;

    // ---- staging maps: 4 uint4 per thread (128 kp x 8 b-pairs) ----
    int    sIdx[4];
    size_t gIdx[4];
    #pragma unroll
    for (int m = 0; m < 4; m++) {
        int e = tid + m * NTHR;
        int kp = e >> 3;
        int bp = e & 7;
        sIdx[m] = kp * 16 + bp * 2;
        gIdx[m] = (size_t)kp * BB + bbase + bp * 2;
    }

    // ---- epilogue mapping ----
    const int eb = tid >> 4;
    const int eh = tid & 15;
    const float bias1_0 = b_ih1[0 * HH + hbase + eh] + b_hh1[0 * HH + hbase + eh];
    const float bias1_1 = b_ih1[1 * HH + hbase + eh] + b_hh1[1 * HH + hbase + eh];
    const float bias1_2 = b_ih1[2 * HH + hbase + eh] + b_hh1[2 * HH + hbase + eh];
    const float bias1_3 = b_ih1[3 * HH + hbase + eh] + b_hh1[3 * HH + hbase + eh];
    float c0acc = c0[(bbase + eb) * HH + hbase + eh];
    float c1acc = c0[(size_t)BB * HH + (bbase + eb) * HH + hbase + eh];

    const unsigned* flg0_grp = &g_flags[bsl * HS];
    const unsigned* flg1_grp = &g_flags[NCTA + bsl * HS];
    unsigned* flg0_self = &g_flags[cta];
    unsigned* flg1_self = &g_flags[NCTA + cta];

    uint4 xpv = *(const uint4*)&g_xp0[(((size_t)0 * BB + bbase + eb) * HH
                                       + hbase + eh) * 4];
    __syncthreads();

    for (int t = 0; t <= TT; t++) {
        const bool do0 = (t < TT);
        const bool do1 = (t > 0);

        // ---- poll phase (R13-identical): batched parallel acquires ----
        if (t > 0) {
            if (tid < HS) {                       // y0(t-1) ready?
                const unsigned* fp = flg0_grp + tid;
                unsigned v;
                do { asm volatile("ld.acquire.gpu.global.u32 %0, [%1];" : "=r"(v) : "l"(fp)); }
                while (v < (unsigned)t);
            } else if (tid < 2 * HS) {            // y1(t-2) ready?
                const unsigned* fp = flg1_grp + (tid - HS);
                unsigned v;
                do { asm volatile("ld.acquire.gpu.global.u32 %0, [%1];" : "=r"(v) : "l"(fp)); }
                while (v < (unsigned)(t - 1));
            }
            __syncthreads();   // SYNC0
        }

        // ---- stage A := y0(t-1) (or L0 h-init); THEN issue y1(t-2) LDGs ----
        uint4 xr[4];                     // R17 change: register-buffered fetch
        if (t == 0) {
            #pragma unroll
            for (int m = 0; m < 8; m++) {
                int e = tid + m * NTHR;
                int kp = e >> 4, b = e & 15;
                A[kp * 16 + b] = ((const float2*)h0)[(size_t)(bbase + b) * HP + kp];
            }
        } else {
            const float2* src = g_y0 + (size_t)(t - 1) * HP * BB;
            #pragma unroll
            for (int m = 0; m < 4; m++)
                *(uint4*)&A[sIdx[m]] = *(const uint4*)&src[gIdx[m]];
        }
        if (t >= 2) {                    // lands under the ~4K-cycle GEMM phase
            const float2* src1 = g_y1 + (size_t)(t - 2) * HP * BB;
            #pragma unroll
            for (int m = 0; m < 4; m++)
                xr[m] = *(const uint4*)&src1[gIdx[m]];
        }
        __syncthreads();   // SYNC1

        // xp0 prefetch for epi0 (consumed after SYNC3 — big slack)
        uint4 xv = make_uint4(0u, 0u, 0u, 0u);
        if (do0)
            xv = *(const uint4*)&g_xp0[(((size_t)t * BB + bbase + eb) * HH
                                        + hbase + eh) * 4];

        uint64_t acc0[4][4] = {};
        uint64_t acc1[4][4] = {};
        if (do0) gemm32(Wp0 + wOff, A + aOff, acc0);        // L0 h-GEMM(t)
        if (do1) gemm32(Wp1 + wOff, A + aOff, acc1);        // L1 x-GEMM(t-1)
        __syncthreads();   // SYNC2 (A consumed)

        // ---- restage A := y1(t-2) (pure STS from regs); P := acc0 ----
        if (do1) {
            if (t == 1) {
                const float2* h1i = (const float2*)(h0 + (size_t)BB * HH);
                #pragma unroll
                for (int m = 0; m < 8; m++) {
                    int e = tid + m * NTHR;
                    int kp = e >> 4, b = e & 15;
                    A[kp * 16 + b] = h1i[(size_t)(bbase + b) * HP + kp];
                }
            } else {
                #pragma unroll
                for (int m = 0; m < 4; m++)
                    *(uint4*)&A[sIdx[m]] = xr[m];
            }
        }
        if (do0) {
            float* pb = P + kg * (16 * PJ) + b2 * PJ + jt * 4;
            #pragma unroll
            for (int bi = 0; bi < 4; bi++) {
                union { uint64_t u; float2 f; } a0, a1, a2, a3;
                a0.u = acc0[0][bi]; a1.u = acc0[1][bi];
                a2.u = acc0[2][bi]; a3.u = acc0[3][bi];
                float4 v;
                v.x = a0.f.x + a0.f.y; v.y = a1.f.x + a1.f.y;
                v.z = a2.f.x + a2.f.y; v.w = a3.f.x + a3.f.y;
                *(float4*)(pb + bi * PJ) = v;
            }
        }
        __syncthreads();   // SYNC3

        if (do1) gemm32(Wp1 + (size_t)128 * 64 + wOff, A + aOff, acc1);  // L1 h-GEMM

        // ---- epi0 (reads P + xp0) ----
        if (do0) {
            float4 xf = *(float4*)&xv;
            float s0 = xf.x, s1 = xf.y, s2 = xf.z, s3 = xf.w;
            #pragma unroll
            for (int p = 0; p < 4; p++) {
                const float* pp = P + p * (16 * PJ) + eb * PJ;
                s0 += pp[ 0 + eh];
                s1 += pp[16 + eh];
                s2 += pp[32 + eh];
                s3 += pp[48 + eh];
            }
            const float ig = fast_sigmoid(s0);
            const float fg = fast_sigmoid(s1);
            const float gt = fast_tanh(s2);
            const float og = fast_sigmoid(s3);
            c0acc = fg * c0acc + ig * gt;
            const float hv = og * fast_tanh(c0acc);
            const float hv1 = __shfl_down_sync(0xffffffffu, hv, 1);
            if (!(eh & 1))
                g_y0[(size_t)t * HP * BB + ((hbase + eh) >> 1) * BB + (bbase + eb)] =
                    make_float2(hv, hv1);
            if (t == TT - 1) {
                hn[(bbase + eb) * HH + hbase + eh] = hv;
                cn[(bbase + eb) * HH + hbase + eh] = c0acc;
            }
        }
        __syncthreads();   // SYNC4 (y0 stores + P reads done)
        if (tid == 0 && t < TT)
            asm volatile("st.release.gpu.global.u32 [%0], %1;"
                         :: "l"(flg0_self), "r"((unsigned)(t + 1)) : "memory");

        // ---- P := acc1 ----
        if (do1) {
            float* pb = P + kg * (16 * PJ) + b2 * PJ + jt * 4;
            #pragma unroll
            for (int bi = 0; bi < 4; bi++) {
                union { uint64_t u; float2 f; } a0, a1, a2, a3;
                a0.u = acc1[0][bi]; a1.u = acc1[1][bi];
                a2.u = acc1[2][bi]; a3.u = acc1[3][bi];
                float4 v;
                v.x = a0.f.x + a0.f.y; v.y = a1.f.x + a1.f.y;
                v.z = a2.f.x + a2.f.y; v.w = a3.f.x + a3.f.y;
                *(float4*)(pb + bi * PJ) = v;
            }
        }
        __syncthreads();   // SYNC5

        // ---- epi1 ----
        if (do1) {
            float s0 = bias1_0, s1 = bias1_1, s2 = bias1_2, s3 = bias1_3;
            #pragma unroll
            for (int p = 0; p < 4; p++) {
                const float* pp = P + p * (16 * PJ) + eb * PJ;
                s0 += pp[ 0 + eh];
                s1 += pp[16 + eh];
                s2 += pp[32 + eh];
                s3 += pp[48 + eh];
            }
            const float ig = fast_sigmoid(s0);
            const float fg = fast_sigmoid(s1);
            const float gt = fast_tanh(s2);
            const float og = fast_sigmoid(s3);
            c1acc = fg * c1acc + ig * gt;
            const float hv = og * fast_tanh(c1acc);
            const float hv1 = __shfl_down_sync(0xffffffffu, hv, 1);
            if (!(eh & 1))
                g_y1[(size_t)(t - 1) * HP * BB + ((hbase + eh) >> 1) * BB + (bbase + eb)] =
                    make_float2(hv, hv1);
            if (t - 1 == TT - 1) {
                hn[(size_t)BB * HH + (bbase + eb) * HH + hbase + eh] = hv;
                cn[(size_t)BB * HH + (bbase + eb) * HH + hbase + eh] = c1acc;
            }
        }
        __syncthreads();   // SYNC6 (y1 stores + P reads done)
        if (tid == 0 && t > 0)
            asm volatile("st.release.gpu.global.u32 [%0], %1;"
                         :: "l"(flg1_self), "r"((unsigned)t) : "memory");
    }
}

// Final projection + softplus: out[t][b][o] = softplus(y1[t]·W_out^T + b_out)
__global__ void __launch_bounds__(128, 4)
proj_kernel(const float* __restrict__ W_out,  // (33, 256)
            const float* __restrict__ b_out,  // (33,)
            float* __restrict__ out)          // [T][B][33]
{
    __shared__ float Wsm[HH * OO];
    const int t = blockIdx.x;
    const int b = threadIdx.x;

    for (int i = b; i < HH * OO; i += 128) {
        int k = i / OO;
        int o = i - k * OO;
        Wsm[k * OO + o] = W_out[o * HH + k];
    }
    __syncthreads();

    const float2* y = g_y1 + (size_t)t * HP * BB;
    float acc[OO];
    #pragma unroll
    for (int o = 0; o < OO; o++) acc[o] = b_out[o];

    #pragma unroll 2
    for (int kp = 0; kp < HP; kp++) {
        const float2 v = y[kp * BB + b];
        const float* w0 = &Wsm[(2 * kp) * OO];
        const float* w1 = &Wsm[(2 * kp + 1) * OO];
        #pragma unroll
        for (int o = 0; o < OO; o++) acc[o] += v.x * w0[o] + v.y * w1[o];
    }

    float* op = out + (size_t)t * BB * OO + b * OO;
    #pragma unroll
    for (int o = 0; o < OO; o++) {
        const float x = acc[o];
        op[o] = fmaxf(x, 0.f) + log1pf(__expf(-fabsf(x)));
    }
}

extern "C" void kernel_launch(void* const* d_in, const int* in_sizes, int n_in,
                              void* d_out, int out_size) {
    const float* x     = (const float*)d_in[0];
    const float* h0    = (const float*)d_in[1];
    const float* c0    = (const float*)d_in[2];
    const float* W_ih0 = (const float*)d_in[3];
    const float* W_hh0 = (const float*)d_in[4];
    const float* b_ih0 = (const float*)d_in[5];
    const float* b_hh0 = (const float*)d_in[6];
    const float* W_ih1 = (const float*)d_in[7];
    const float* W_hh1 = (const float*)d_in[8];
    const float* b_ih1 = (const float*)d_in[9];
    const float* b_hh1 = (const float*)d_in[10];
    const float* W_out = (const float*)d_in[11];
    const float* b_out = (const float*)d_in[12];

    float* out = (float*)d_out;
    float* hn  = out + (size_t)TT * BB * OO;   // (2,B,H)
    float* cn  = hn + 2 * BB * HH;             // (2,B,H)

    // smem: Wp0 64K + Wp1 128K + A 16K + P 4*16*68*4 = 230,400 B
    const int smemF = 128 * 64 * 8 + 256 * 64 * 8 + 128 * 16 * 8 + 4 * 16 * PJ * 4;
    cudaFuncSetAttribute((const void*)lstm_fused_kernel,
                         cudaFuncAttributeMaxDynamicSharedMemorySize, smemF);

    reset_kernel<<<1, 256>>>();

    dim3 xg(TT, 8, 2);
    xp0_kernel<<<xg, 256>>>(x, W_ih0, b_ih0, b_hh0);

    lstm_fused_kernel<<<NCTA, NTHR, smemF>>>(
        W_hh0, W_ih1, W_hh1, b_ih1, b_hh1, h0, c0, hn, cn);

    proj_kernel<<<TT, 128>>>(W_out, b_out, out);
}